// round 14
// baseline (speedup 1.0000x reference)
#include <cuda_runtime.h>
#include <cuda_fp16.h>
#include <cstdint>

#define NN     8192
#define F_IN   128
#define F_OUTD 64
#define L2E    1.4426950408889634f

#define ALPHA2_PK 0x32663266u   // half2(0.2, 0.2)
#define MESH2_PK  0xC5C5C5C5u   // half2(-5.7695, -5.7695) (~ -4*log2(e); uniform
                                // offset, cancels exactly in softmax)

// ---------------------------------------------------------------------------
// Device scratch (allocations forbidden -> __device__ globals)
// ---------------------------------------------------------------------------
__device__ __half   g_whT16[F_OUTD * NN];    // [f][i] fp16 transpose of wh
__device__ float    g_src[NN];
__device__ __half   g_dst16h[NN];            // dst[i] * L2E as fp16
__device__ float    g_part[256 * 128 * 68];  // [cta][row][64 num, Z, pad..]
__device__ int      g_sem[64];               // per-row-block arrival counters
                                             // (zero-init; finisher resets)

// ---------------------------------------------------------------------------
// Kernel 1: WH = H @ W, fp16 transpose WH^T, AND src/dst vectors (fused).
// 32 rows per block. g_wh fp32 is never materialized.
// ---------------------------------------------------------------------------
__global__ __launch_bounds__(256) void prep_kernel(const float* __restrict__ h,
                                                   const float* __restrict__ w,
                                                   const float* __restrict__ edge,
                                                   const float* __restrict__ att,
                                                   const float* __restrict__ w_edge) {
    __shared__ __align__(16) float sW[F_IN * F_OUTD];  // 32 KB
    __shared__ __align__(16) float sH[32 * F_IN];      // 16 KB (reused: sT + red)
    int t = threadIdx.x;
    int i0 = blockIdx.x * 32;
    int lane = t & 31, warp = t >> 5;

    {
        float4* dw = (float4*)sW;
        const float4* swg = (const float4*)w;
        #pragma unroll
        for (int k = 0; k < 8; k++) dw[t + k * 256] = swg[t + k * 256];
        float4* dh = (float4*)sH;
        const float4* shg = (const float4*)(h + (size_t)i0 * F_IN);
        #pragma unroll
        for (int k = 0; k < 4; k++) dh[t + k * 256] = shg[t + k * 256];
    }
    __syncthreads();

    int f = t & 63;
    int rg = t >> 6;   // rows rg*8 .. rg*8+7 (warp pair 2rg, 2rg+1)
    float acc[8] = {0.f, 0.f, 0.f, 0.f, 0.f, 0.f, 0.f, 0.f};
    #pragma unroll 4
    for (int k = 0; k < F_IN; k += 4) {
        float w0 = sW[(k + 0) * F_OUTD + f];
        float w1 = sW[(k + 1) * F_OUTD + f];
        float w2 = sW[(k + 2) * F_OUTD + f];
        float w3 = sW[(k + 3) * F_OUTD + f];
        #pragma unroll
        for (int m = 0; m < 8; m++) {
            float4 h4 = *(const float4*)&sH[(rg * 8 + m) * F_IN + k];
            acc[m] = fmaf(h4.x, w0, acc[m]);
            acc[m] = fmaf(h4.y, w1, acc[m]);
            acc[m] = fmaf(h4.z, w2, acc[m]);
            acc[m] = fmaf(h4.w, w3, acc[m]);
        }
    }

    // src/dst partials: shuffle-reduce over this warp's 32 features
    float a1 = att[f], a2 = att[64 + f];
    float cpart = w_edge[f] * att[128 + f];
    #pragma unroll
    for (int o = 16; o; o >>= 1) cpart += __shfl_xor_sync(0xffffffffu, cpart, o);
    float sred[8], dred[8];
    #pragma unroll
    for (int m = 0; m < 8; m++) {
        float sp = acc[m] * a1, dp = acc[m] * a2;
        #pragma unroll
        for (int o = 16; o; o >>= 1) {
            sp += __shfl_xor_sync(0xffffffffu, sp, o);
            dp += __shfl_xor_sync(0xffffffffu, dp, o);
        }
        sred[m] = sp; dred[m] = dp;
    }
    // red area: sH + 8KB (past the 4KB sT overlay), written by lane 0
    float* red  = (float*)sH + 2048;   // [warp][m][2]
    float* redc = red + 128;           // [warp]
    if (lane == 0) {
        #pragma unroll
        for (int m = 0; m < 8; m++) {
            red[(warp * 8 + m) * 2 + 0] = sred[m];
            red[(warp * 8 + m) * 2 + 1] = dred[m];
        }
        redc[warp] = cpart;
    }
    __syncthreads();   // orders: acc->sT overwrite, red writes -> red reads

    // fp16 transpose staging into sT (sH bytes 0..4095)
    __half* sT = (__half*)sH;   // [64 f][32 r]
    #pragma unroll
    for (int m = 0; m < 8; m++)
        sT[f * 32 + rg * 8 + m] = __float2half_rn(acc[m]);

    // src/dst finalize (threads 0..31, one row each; disjoint from sT region)
    if (t < 32) {
        int rr = t;
        int wp = 2 * (rr >> 3);
        int m = rr & 7;
        float s = red[(wp * 8 + m) * 2 + 0] + red[((wp + 1) * 8 + m) * 2 + 0];
        float d = red[(wp * 8 + m) * 2 + 1] + red[((wp + 1) * 8 + m) * 2 + 1];
        float c3 = redc[0] + redc[1];
        g_src[i0 + rr] = s + edge[i0 + rr] * c3;
        g_dst16h[i0 + rr] = __float2half_rn(d * L2E);
    }
    __syncthreads();
    {
        int f2 = t >> 2, seg = t & 3;
        uint4 v = *(const uint4*)(sT + f2 * 32 + seg * 8);
        *(uint4*)(g_whT16 + (size_t)f2 * NN + i0 + seg * 8) = v;
    }
}

// ---------------------------------------------------------------------------
// mma.sync / ldmatrix / cp.async helpers
// ---------------------------------------------------------------------------
__device__ __forceinline__ uint32_t smem_u32(const void* p) {
    uint32_t a;
    asm("{ .reg .u64 t; cvta.to.shared.u64 t, %1; cvt.u32.u64 %0, t; }"
        : "=r"(a) : "l"(p));
    return a;
}
__device__ __forceinline__ void mma16816(float* c, uint32_t a0, uint32_t a1,
                                         uint32_t a2, uint32_t a3,
                                         uint32_t b0, uint32_t b1) {
    asm volatile(
        "mma.sync.aligned.m16n8k16.row.col.f32.f16.f16.f32 "
        "{%0,%1,%2,%3}, {%4,%5,%6,%7}, {%8,%9}, {%0,%1,%2,%3};"
        : "+f"(c[0]), "+f"(c[1]), "+f"(c[2]), "+f"(c[3])
        : "r"(a0), "r"(a1), "r"(a2), "r"(a3), "r"(b0), "r"(b1));
}
__device__ __forceinline__ void ldsm_x4(uint32_t* r, uint32_t addr) {
    asm volatile("ldmatrix.sync.aligned.m8n8.x4.shared.b16 {%0,%1,%2,%3}, [%4];"
                 : "=r"(r[0]), "=r"(r[1]), "=r"(r[2]), "=r"(r[3]) : "r"(addr));
}
__device__ __forceinline__ void cp_async16(uint32_t saddr, const void* gaddr) {
    asm volatile("cp.async.cg.shared.global [%0], [%1], 16;"
                 :: "r"(saddr), "l"(gaddr) : "memory");
}
__device__ __forceinline__ void cp_commit() {
    asm volatile("cp.async.commit_group;" ::: "memory");
}
__device__ __forceinline__ void cp_wait7() {
    asm volatile("cp.async.wait_group 7;" ::: "memory");
}
__device__ __forceinline__ int4 lds128(uint32_t addr) {
    int4 v;
    asm volatile("ld.shared.v4.u32 {%0,%1,%2,%3}, [%4];"
                 : "=r"(v.x), "=r"(v.y), "=r"(v.z), "=r"(v.w) : "r"(addr));
    return v;
}
// packed fp16 attention pair: src2/d2 already *L2E; mask by multiply.
__device__ __forceinline__ uint32_t wpair16(uint32_t src2, uint32_t d2,
                                            int ax, int ay) {
    uint32_t e, m, l, g, w;
    asm("add.f16x2 %0, %1, %2;"    : "=r"(e) : "r"(src2), "r"(d2));
    asm("mul.f16x2 %0, %1, %2;"    : "=r"(m) : "r"(e), "r"(ALPHA2_PK));
    asm("max.f16x2 %0, %1, %2;"    : "=r"(l) : "r"(e), "r"(m));
    asm("add.f16x2 %0, %1, %2;"    : "=r"(g) : "r"(l), "r"(MESH2_PK));
    asm("ex2.approx.f16x2 %0, %0;" : "+r"(g));
    uint32_t msk = (uint32_t)ax * 0x3C00u + (uint32_t)ay * 0x3C000000u;
    asm("mul.f16x2 %0, %1, %2;"    : "=r"(w) : "r"(g), "r"(msk));
    return w;
}

// ---------------------------------------------------------------------------
// Kernel 2: HMMA masked-softmax aggregation (round-13 core) + INLINE combine.
// The last of the 4 j-quarter CTAs per row-block (arrival counter g_sem)
// performs normalize+ELU for its 128 rows — overlapping combine with the
// attn tail and removing the separate kernel + full-grid barrier.
// Dynamic smem 96 KB: [0,64K) adj ring (8 warps x 8KB), [64K,96K) B dbl-buf.
// ---------------------------------------------------------------------------
__global__ void __launch_bounds__(256, 2) attn_kernel(const int* __restrict__ adj,
                                                      float* __restrict__ out) {
    extern __shared__ __align__(1024) char sm[];
    char* sBreg = sm + 65536;                     // 2 x 16 KB B buffers

    int t = threadIdx.x, lane = t & 31, w = t >> 5;
    int bx = blockIdx.x;
    int i0 = (bx >> 2) * 128, j0 = (bx & 3) * 2048;

    int l4 = lane & 3;
    int lr = lane >> 2;
    int row0 = w * 16 + lr;

    float acc[8][4];
    float zc[4];
    #pragma unroll
    for (int p = 0; p < 8; p++)
        #pragma unroll
        for (int q = 0; q < 4; q++) acc[p][q] = 0.f;
    #pragma unroll
    for (int q = 0; q < 4; q++) zc[q] = 0.f;

    // src * L2E, replicated half2
    __half2 s0h = __float2half2_rn(g_src[i0 + row0] * L2E);
    __half2 s1h = __float2half2_rn(g_src[i0 + row0 + 8] * L2E);
    uint32_t srcL0 = *(const uint32_t*)&s0h;
    uint32_t srcL1 = *(const uint32_t*)&s1h;

    // adjacency: lane's global stream (one int4 per k-step per row-half)
    const int* gL = adj + (size_t)(i0 + row0) * NN + j0 + l4 * 4;
    const int* gH = gL + (size_t)8 * NN;
    // warp-private ring slab + per-lane offsets (lane-linear -> conflict-free)
    uint32_t sadj = smem_u32(sm) + (uint32_t)w * 8192u;
    uint32_t aoffL = (uint32_t)(lr * 64 + l4 * 16);
    uint32_t aoffH = aoffL + 512u;
    // dst base: half2 units
    const uint32_t* dpp = (const uint32_t*)g_dst16h + (j0 >> 1) + l4 * 2;

    // B-copy indices
    int fB = t >> 2, qb = (t & 3) * 4;
    const uint4* bsrc_base = (const uint4*)(g_whT16 + (size_t)fB * NN + j0);
    // ldmatrix per-lane geometry
    int fo  = (lane & 7) + ((lane & 16) >> 1);
    int cb  = (lane >> 3) & 1;
    int sw7 = lane & 7;
    uint32_t sb_base = smem_u32(sm) + 65536u;

    // prologue: adj ring slots 0..7 (= steps 0..7), one commit group per step
    #pragma unroll
    for (int st = 0; st < 8; st++) {
        cp_async16(sadj + (uint32_t)st * 1024u + aoffL, gL + st * 16);
        cp_async16(sadj + (uint32_t)st * 1024u + aoffH, gH + st * 16);
        cp_commit();
    }
    // dst ring prologue (L2-resident, register ring depth 2)
    uint2 rD[2];
    rD[0] = *(const uint2*)(dpp);
    rD[1] = *(const uint2*)(dpp + 8);
    // B buffer 0 (direct stage: load + deinterleave + store)
    {
        uint4 v0 = bsrc_base[qb], v1 = bsrc_base[qb + 1];
        uint4 v2 = bsrc_base[qb + 2], v3 = bsrc_base[qb + 3];
        char* db = sBreg + (size_t)fB * 256;
        uint4 o0 = make_uint4(v0.x, v0.z, v1.x, v1.z);
        uint4 o1 = make_uint4(v0.y, v0.w, v1.y, v1.w);
        uint4 o2 = make_uint4(v2.x, v2.z, v3.x, v3.z);
        uint4 o3 = make_uint4(v2.y, v2.w, v3.y, v3.w);
        *(uint4*)(db + (((qb + 0) ^ (fB & 7)) << 4)) = o0;
        *(uint4*)(db + (((qb + 1) ^ (fB & 7)) << 4)) = o1;
        *(uint4*)(db + (((qb + 2) ^ (fB & 7)) << 4)) = o2;
        *(uint4*)(db + (((qb + 3) ^ (fB & 7)) << 4)) = o3;
    }

    // first consumer registers: slot 0 (group 0 done after wait<=7)
    cp_wait7();
    int4 c0L = lds128(sadj + aoffL);
    int4 c0H = lds128(sadj + aoffH);
    int4 c1L, c1H;

    const uint32_t ONES = 0x3C003C00u;  // fp16 {1,1}

    #define STEP(ks)                                                            \
        do {                                                                    \
            int4 aL = ((ks) & 1) ? c1L : c0L;                                   \
            int4 aH = ((ks) & 1) ? c1H : c0H;                                   \
            uint2 dd = rD[(ks) & 1];                                            \
            if (refill) {                                                       \
                cp_async16(sadj + (uint32_t)(ks) * 1024u + aoffL,               \
                           gLt + (ks) * 16);                                    \
                cp_async16(sadj + (uint32_t)(ks) * 1024u + aoffH,               \
                           gHt + (ks) * 16);                                    \
            }                                                                   \
            cp_commit();                                                        \
            if (refill || (ks) < 6)                                             \
                rD[(ks) & 1] = *(const uint2*)(dpp + (gbase + (ks) + 2) * 8);   \
            cp_wait7();                                                         \
            {                                                                   \
                uint32_t na = sadj + (uint32_t)(((ks) + 1) & 7) * 1024u;        \
                if ((ks) & 1) { c0L = lds128(na + aoffL);                       \
                                c0H = lds128(na + aoffH); }                     \
                else          { c1L = lds128(na + aoffL);                       \
                                c1H = lds128(na + aoffH); }                     \
            }                                                                   \
            uint32_t fa0 = wpair16(srcL0, dd.x, aL.x, aL.y);                    \
            uint32_t fa1 = wpair16(srcL1, dd.x, aH.x, aH.y);                    \
            uint32_t fa2 = wpair16(srcL0, dd.y, aL.z, aL.w);                    \
            uint32_t fa3 = wpair16(srcL1, dd.y, aH.z, aH.w);                    \
            uint32_t chx = (uint32_t)(((2 * (ks) + cb) ^ sw7) << 4);            \
            uint32_t b[16];                                                     \
            _Pragma("unroll")                                                   \
            for (int pp = 0; pp < 4; pp++)                                      \
                ldsm_x4(b + pp * 4, lmbase + (uint32_t)(pp * 4096) + chx);      \
            _Pragma("unroll")                                                   \
            for (int p = 0; p < 8; p++)                                         \
                mma16816(acc[p], fa0, fa1, fa2, fa3, b[p * 2], b[p * 2 + 1]);   \
            mma16816(zc, fa0, fa1, fa2, fa3, ONES, ONES);                       \
        } while (0)

    for (int lt = 0; lt < 16; lt++) {
        int s = lt & 1;
        __syncthreads();

        // issue next-tile B loads NOW; store after step 2
        uint4 v0, v1, v2, v3;
        bool refill = (lt < 15);
        if (refill) {
            const uint4* bs = bsrc_base + (lt + 1) * 16;
            v0 = bs[qb]; v1 = bs[qb + 1]; v2 = bs[qb + 2]; v3 = bs[qb + 3];
        }

        uint32_t lmbase = sb_base + (uint32_t)s * 16384u + (uint32_t)fo * 256u;
        int gbase = lt * 8;
        const int* gLt = gL + (gbase + 8) * 16;
        const int* gHt = gH + (gbase + 8) * 16;

        STEP(0); STEP(1); STEP(2);

        if (refill) {   // B deinterleave + store, ~350 cyc after the loads
            char* db = sBreg + (s ^ 1) * 16384 + (size_t)fB * 256;
            uint4 o0 = make_uint4(v0.x, v0.z, v1.x, v1.z);
            uint4 o1 = make_uint4(v0.y, v0.w, v1.y, v1.w);
            uint4 o2 = make_uint4(v2.x, v2.z, v3.x, v3.z);
            uint4 o3 = make_uint4(v2.y, v2.w, v3.y, v3.w);
            *(uint4*)(db + (((qb + 0) ^ (fB & 7)) << 4)) = o0;
            *(uint4*)(db + (((qb + 1) ^ (fB & 7)) << 4)) = o1;
            *(uint4*)(db + (((qb + 2) ^ (fB & 7)) << 4)) = o2;
            *(uint4*)(db + (((qb + 3) ^ (fB & 7)) << 4)) = o3;
        }

        STEP(3); STEP(4); STEP(5); STEP(6); STEP(7);
    }
    #undef STEP

    // epilogue: C frags -> g_part (stride 68, float2-aligned)
    size_t rbase = (size_t)bx * 128 + row0;
    #pragma unroll
    for (int p = 0; p < 8; p++) {
        float* o0 = g_part + rbase * 68 + p * 8 + l4 * 2;
        float* o1 = o0 + 8 * 68;
        *(float2*)o0 = make_float2(acc[p][0], acc[p][1]);
        *(float2*)o1 = make_float2(acc[p][2], acc[p][3]);
    }
    if (l4 == 0) {
        g_part[rbase * 68 + 64] = zc[0];
        g_part[(rbase + 8) * 68 + 64] = zc[2];
    }

    // ---- inline combine: last-arriving quarter CTA finishes the row-block ----
    int rb = bx >> 2;
    __threadfence();            // release our g_part writes
    __syncthreads();
    int* flag = (int*)sm;       // adj ring region is dead now
    if (t == 0) {
        int old = atomicAdd(&g_sem[rb], 1);
        flag[0] = (old == 3);
    }
    __syncthreads();
    if (flag[0]) {
        __threadfence();        // acquire the other quarters' g_part writes
        const float* pb = g_part + (size_t)(rb * 4) * 128 * 68;
        #pragma unroll
        for (int k = 0; k < 8; k++) {
            int u = t + k * 256;        // 0..2047 float4 units
            int i = u >> 4, fq = u & 15;
            const float* p = pb + (size_t)i * 68 + fq * 4;
            const float* pz = pb + (size_t)i * 68 + 64;
            float nx = 0.f, ny = 0.f, nz = 0.f, nw = 0.f, z = 0.f;
            #pragma unroll
            for (int q = 0; q < 4; q++) {
                float4 v = *(const float4*)(p + (size_t)q * 128 * 68);
                nx += v.x; ny += v.y; nz += v.z; nw += v.w;
                z += pz[(size_t)q * 128 * 68];
            }
            float4 o;
            o.x = nx / z; o.y = ny / z; o.z = nz / z; o.w = nw / z;
            o.x = (o.x > 0.f) ? o.x : expm1f(o.x);
            o.y = (o.y > 0.f) ? o.y : expm1f(o.y);
            o.z = (o.z > 0.f) ? o.z : expm1f(o.z);
            o.w = (o.w > 0.f) ? o.w : expm1f(o.w);
            *(float4*)(out + ((size_t)rb * 128 + i) * F_OUTD + fq * 4) = o;
        }
        if (t == 0) g_sem[rb] = 0;   // reset for next graph replay
    }
}

// ---------------------------------------------------------------------------
// Launch. Inputs: 0 h_nodes(8192x128 f32), 1 edge(8192 f32), 2 adj(8192^2 i32),
//                 3 weight(128x64 f32), 4 att(192 f32), 5 w_edge(64 f32)
// ---------------------------------------------------------------------------
extern "C" void kernel_launch(void* const* d_in, const int* in_sizes, int n_in,
                              void* d_out, int out_size) {
    const float* h      = (const float*)d_in[0];
    const float* edge   = (const float*)d_in[1];
    const int*   adj    = (const int*)d_in[2];
    const float* weight = (const float*)d_in[3];
    const float* att    = (const float*)d_in[4];
    const float* w_edge = (const float*)d_in[5];
    float* out = (float*)d_out;

    cudaFuncSetAttribute(attn_kernel,
                         cudaFuncAttributeMaxDynamicSharedMemorySize, 98304);

    prep_kernel<<<NN / 32, 256>>>(h, weight, edge, att, w_edge);
    attn_kernel<<<256, 256, 98304>>>(adj, out);
}

// round 15
// speedup vs baseline: 1.0697x; 1.0697x over previous
#include <cuda_runtime.h>
#include <cuda_fp16.h>
#include <cstdint>

#define NN     8192
#define F_IN   128
#define F_OUTD 64
#define L2E    1.4426950408889634f

#define ALPHA2_PK 0x32663266u   // half2(0.2, 0.2)
#define MESH2_PK  0xC5C5C5C5u   // half2(-5.7695, -5.7695) (~ -4*log2(e); uniform
                                // offset, cancels exactly in softmax)

// ---------------------------------------------------------------------------
// Device scratch (allocations forbidden -> __device__ globals)
// ---------------------------------------------------------------------------
__device__ __half   g_whT16[F_OUTD * NN];    // [f][i] fp16 transpose of wh
__device__ float    g_src[NN];
__device__ __half   g_dst16h[NN];            // dst[i] * L2E as fp16
__device__ float    g_part[256 * 128 * 68];  // [cta][row][64 num, Z, pad..]

// ---------------------------------------------------------------------------
// Kernel 1: WH = H @ W, fp16 transpose WH^T, AND src/dst vectors (fused).
// 32 rows per block. g_wh fp32 is never materialized.
// ---------------------------------------------------------------------------
__global__ __launch_bounds__(256) void prep_kernel(const float* __restrict__ h,
                                                   const float* __restrict__ w,
                                                   const float* __restrict__ edge,
                                                   const float* __restrict__ att,
                                                   const float* __restrict__ w_edge) {
    __shared__ __align__(16) float sW[F_IN * F_OUTD];  // 32 KB
    __shared__ __align__(16) float sH[32 * F_IN];      // 16 KB (reused: sT + red)
    int t = threadIdx.x;
    int i0 = blockIdx.x * 32;
    int lane = t & 31, warp = t >> 5;

    {
        float4* dw = (float4*)sW;
        const float4* swg = (const float4*)w;
        #pragma unroll
        for (int k = 0; k < 8; k++) dw[t + k * 256] = swg[t + k * 256];
        float4* dh = (float4*)sH;
        const float4* shg = (const float4*)(h + (size_t)i0 * F_IN);
        #pragma unroll
        for (int k = 0; k < 4; k++) dh[t + k * 256] = shg[t + k * 256];
    }
    __syncthreads();

    int f = t & 63;
    int rg = t >> 6;   // rows rg*8 .. rg*8+7 (warp pair 2rg, 2rg+1)
    float acc[8] = {0.f, 0.f, 0.f, 0.f, 0.f, 0.f, 0.f, 0.f};
    #pragma unroll 4
    for (int k = 0; k < F_IN; k += 4) {
        float w0 = sW[(k + 0) * F_OUTD + f];
        float w1 = sW[(k + 1) * F_OUTD + f];
        float w2 = sW[(k + 2) * F_OUTD + f];
        float w3 = sW[(k + 3) * F_OUTD + f];
        #pragma unroll
        for (int m = 0; m < 8; m++) {
            float4 h4 = *(const float4*)&sH[(rg * 8 + m) * F_IN + k];
            acc[m] = fmaf(h4.x, w0, acc[m]);
            acc[m] = fmaf(h4.y, w1, acc[m]);
            acc[m] = fmaf(h4.z, w2, acc[m]);
            acc[m] = fmaf(h4.w, w3, acc[m]);
        }
    }

    // src/dst partials: shuffle-reduce over this warp's 32 features
    float a1 = att[f], a2 = att[64 + f];
    float cpart = w_edge[f] * att[128 + f];
    #pragma unroll
    for (int o = 16; o; o >>= 1) cpart += __shfl_xor_sync(0xffffffffu, cpart, o);
    float sred[8], dred[8];
    #pragma unroll
    for (int m = 0; m < 8; m++) {
        float sp = acc[m] * a1, dp = acc[m] * a2;
        #pragma unroll
        for (int o = 16; o; o >>= 1) {
            sp += __shfl_xor_sync(0xffffffffu, sp, o);
            dp += __shfl_xor_sync(0xffffffffu, dp, o);
        }
        sred[m] = sp; dred[m] = dp;
    }
    // red area: sH + 8KB (past the 4KB sT overlay), written by lane 0
    float* red  = (float*)sH + 2048;   // [warp][m][2]
    float* redc = red + 128;           // [warp]
    if (lane == 0) {
        #pragma unroll
        for (int m = 0; m < 8; m++) {
            red[(warp * 8 + m) * 2 + 0] = sred[m];
            red[(warp * 8 + m) * 2 + 1] = dred[m];
        }
        redc[warp] = cpart;
    }
    __syncthreads();   // orders: acc->sT overwrite, red writes -> red reads

    // fp16 transpose staging into sT (sH bytes 0..4095)
    __half* sT = (__half*)sH;   // [64 f][32 r]
    #pragma unroll
    for (int m = 0; m < 8; m++)
        sT[f * 32 + rg * 8 + m] = __float2half_rn(acc[m]);

    // src/dst finalize (threads 0..31, one row each; disjoint from sT region)
    if (t < 32) {
        int rr = t;
        int wp = 2 * (rr >> 3);
        int m = rr & 7;
        float s = red[(wp * 8 + m) * 2 + 0] + red[((wp + 1) * 8 + m) * 2 + 0];
        float d = red[(wp * 8 + m) * 2 + 1] + red[((wp + 1) * 8 + m) * 2 + 1];
        float c3 = redc[0] + redc[1];
        g_src[i0 + rr] = s + edge[i0 + rr] * c3;
        g_dst16h[i0 + rr] = __float2half_rn(d * L2E);
    }
    __syncthreads();
    {
        int f2 = t >> 2, seg = t & 3;
        uint4 v = *(const uint4*)(sT + f2 * 32 + seg * 8);
        *(uint4*)(g_whT16 + (size_t)f2 * NN + i0 + seg * 8) = v;
    }
}

// ---------------------------------------------------------------------------
// mma.sync / ldmatrix / cp.async helpers
// ---------------------------------------------------------------------------
__device__ __forceinline__ uint32_t smem_u32(const void* p) {
    uint32_t a;
    asm("{ .reg .u64 t; cvta.to.shared.u64 t, %1; cvt.u32.u64 %0, t; }"
        : "=r"(a) : "l"(p));
    return a;
}
__device__ __forceinline__ void mma16816(float* c, uint32_t a0, uint32_t a1,
                                         uint32_t a2, uint32_t a3,
                                         uint32_t b0, uint32_t b1) {
    asm volatile(
        "mma.sync.aligned.m16n8k16.row.col.f32.f16.f16.f32 "
        "{%0,%1,%2,%3}, {%4,%5,%6,%7}, {%8,%9}, {%0,%1,%2,%3};"
        : "+f"(c[0]), "+f"(c[1]), "+f"(c[2]), "+f"(c[3])
        : "r"(a0), "r"(a1), "r"(a2), "r"(a3), "r"(b0), "r"(b1));
}
__device__ __forceinline__ void ldsm_x4(uint32_t* r, uint32_t addr) {
    asm volatile("ldmatrix.sync.aligned.m8n8.x4.shared.b16 {%0,%1,%2,%3}, [%4];"
                 : "=r"(r[0]), "=r"(r[1]), "=r"(r[2]), "=r"(r[3]) : "r"(addr));
}
__device__ __forceinline__ void cp_async16(uint32_t saddr, const void* gaddr) {
    asm volatile("cp.async.cg.shared.global [%0], [%1], 16;"
                 :: "r"(saddr), "l"(gaddr) : "memory");
}
__device__ __forceinline__ void cp_commit() {
    asm volatile("cp.async.commit_group;" ::: "memory");
}
__device__ __forceinline__ void cp_wait7() {
    asm volatile("cp.async.wait_group 7;" ::: "memory");
}
__device__ __forceinline__ int4 lds128(uint32_t addr) {
    int4 v;
    asm volatile("ld.shared.v4.u32 {%0,%1,%2,%3}, [%4];"
                 : "=r"(v.x), "=r"(v.y), "=r"(v.z), "=r"(v.w) : "r"(addr));
    return v;
}
// packed fp16 attention pair: src2/d2 already *L2E; mask by multiply.
__device__ __forceinline__ uint32_t wpair16(uint32_t src2, uint32_t d2,
                                            int ax, int ay) {
    uint32_t e, m, l, g, w;
    asm("add.f16x2 %0, %1, %2;"    : "=r"(e) : "r"(src2), "r"(d2));
    asm("mul.f16x2 %0, %1, %2;"    : "=r"(m) : "r"(e), "r"(ALPHA2_PK));
    asm("max.f16x2 %0, %1, %2;"    : "=r"(l) : "r"(e), "r"(m));
    asm("add.f16x2 %0, %1, %2;"    : "=r"(g) : "r"(l), "r"(MESH2_PK));
    asm("ex2.approx.f16x2 %0, %0;" : "+r"(g));
    uint32_t msk = (uint32_t)ax * 0x3C00u + (uint32_t)ay * 0x3C000000u;
    asm("mul.f16x2 %0, %1, %2;"    : "=r"(w) : "r"(g), "r"(msk));
    return w;
}

// ---------------------------------------------------------------------------
// Kernel 2: HMMA masked-softmax aggregation — round-13 core, unchanged.
// Grid 256 = 64 row-blocks x 4 j-quarters; 2 CTAs/SM; cp.async.cg adj ring
// depth 8 (slot = ks literal); B staging split (LDG at tile top, STS after
// step 2). Dynamic smem 96 KB: [0,64K) adj ring, [64K,96K) B dbl-buf.
// ---------------------------------------------------------------------------
__global__ void __launch_bounds__(256, 2) attn_kernel(const int* __restrict__ adj) {
    extern __shared__ __align__(1024) char sm[];
    char* sBreg = sm + 65536;                     // 2 x 16 KB B buffers

    int t = threadIdx.x, lane = t & 31, w = t >> 5;
    int bx = blockIdx.x;
    int i0 = (bx >> 2) * 128, j0 = (bx & 3) * 2048;

    int l4 = lane & 3;
    int lr = lane >> 2;
    int row0 = w * 16 + lr;

    float acc[8][4];
    float zc[4];
    #pragma unroll
    for (int p = 0; p < 8; p++)
        #pragma unroll
        for (int q = 0; q < 4; q++) acc[p][q] = 0.f;
    #pragma unroll
    for (int q = 0; q < 4; q++) zc[q] = 0.f;

    // src * L2E, replicated half2
    __half2 s0h = __float2half2_rn(g_src[i0 + row0] * L2E);
    __half2 s1h = __float2half2_rn(g_src[i0 + row0 + 8] * L2E);
    uint32_t srcL0 = *(const uint32_t*)&s0h;
    uint32_t srcL1 = *(const uint32_t*)&s1h;

    // adjacency: lane's global stream (one int4 per k-step per row-half)
    const int* gL = adj + (size_t)(i0 + row0) * NN + j0 + l4 * 4;
    const int* gH = gL + (size_t)8 * NN;
    // warp-private ring slab + per-lane offsets (lane-linear -> conflict-free)
    uint32_t sadj = smem_u32(sm) + (uint32_t)w * 8192u;
    uint32_t aoffL = (uint32_t)(lr * 64 + l4 * 16);
    uint32_t aoffH = aoffL + 512u;
    // dst base: half2 units
    const uint32_t* dpp = (const uint32_t*)g_dst16h + (j0 >> 1) + l4 * 2;

    // B-copy indices
    int fB = t >> 2, qb = (t & 3) * 4;
    const uint4* bsrc_base = (const uint4*)(g_whT16 + (size_t)fB * NN + j0);
    // ldmatrix per-lane geometry
    int fo  = (lane & 7) + ((lane & 16) >> 1);
    int cb  = (lane >> 3) & 1;
    int sw7 = lane & 7;
    uint32_t sb_base = smem_u32(sm) + 65536u;

    // prologue: adj ring slots 0..7 (= steps 0..7), one commit group per step
    #pragma unroll
    for (int st = 0; st < 8; st++) {
        cp_async16(sadj + (uint32_t)st * 1024u + aoffL, gL + st * 16);
        cp_async16(sadj + (uint32_t)st * 1024u + aoffH, gH + st * 16);
        cp_commit();
    }
    // dst ring prologue (L2-resident, register ring depth 2)
    uint2 rD[2];
    rD[0] = *(const uint2*)(dpp);
    rD[1] = *(const uint2*)(dpp + 8);
    // B buffer 0 (direct stage: load + deinterleave + store)
    {
        uint4 v0 = bsrc_base[qb], v1 = bsrc_base[qb + 1];
        uint4 v2 = bsrc_base[qb + 2], v3 = bsrc_base[qb + 3];
        char* db = sBreg + (size_t)fB * 256;
        uint4 o0 = make_uint4(v0.x, v0.z, v1.x, v1.z);
        uint4 o1 = make_uint4(v0.y, v0.w, v1.y, v1.w);
        uint4 o2 = make_uint4(v2.x, v2.z, v3.x, v3.z);
        uint4 o3 = make_uint4(v2.y, v2.w, v3.y, v3.w);
        *(uint4*)(db + (((qb + 0) ^ (fB & 7)) << 4)) = o0;
        *(uint4*)(db + (((qb + 1) ^ (fB & 7)) << 4)) = o1;
        *(uint4*)(db + (((qb + 2) ^ (fB & 7)) << 4)) = o2;
        *(uint4*)(db + (((qb + 3) ^ (fB & 7)) << 4)) = o3;
    }

    // first consumer registers: slot 0 (group 0 done after wait<=7)
    cp_wait7();
    int4 c0L = lds128(sadj + aoffL);
    int4 c0H = lds128(sadj + aoffH);
    int4 c1L, c1H;

    const uint32_t ONES = 0x3C003C00u;  // fp16 {1,1}

    #define STEP(ks)                                                            \
        do {                                                                    \
            int4 aL = ((ks) & 1) ? c1L : c0L;                                   \
            int4 aH = ((ks) & 1) ? c1H : c0H;                                   \
            uint2 dd = rD[(ks) & 1];                                            \
            if (refill) {                                                       \
                cp_async16(sadj + (uint32_t)(ks) * 1024u + aoffL,               \
                           gLt + (ks) * 16);                                    \
                cp_async16(sadj + (uint32_t)(ks) * 1024u + aoffH,               \
                           gHt + (ks) * 16);                                    \
            }                                                                   \
            cp_commit();                                                        \
            if (refill || (ks) < 6)                                             \
                rD[(ks) & 1] = *(const uint2*)(dpp + (gbase + (ks) + 2) * 8);   \
            cp_wait7();                                                         \
            {                                                                   \
                uint32_t na = sadj + (uint32_t)(((ks) + 1) & 7) * 1024u;        \
                if ((ks) & 1) { c0L = lds128(na + aoffL);                       \
                                c0H = lds128(na + aoffH); }                     \
                else          { c1L = lds128(na + aoffL);                       \
                                c1H = lds128(na + aoffH); }                     \
            }                                                                   \
            uint32_t fa0 = wpair16(srcL0, dd.x, aL.x, aL.y);                    \
            uint32_t fa1 = wpair16(srcL1, dd.x, aH.x, aH.y);                    \
            uint32_t fa2 = wpair16(srcL0, dd.y, aL.z, aL.w);                    \
            uint32_t fa3 = wpair16(srcL1, dd.y, aH.z, aH.w);                    \
            uint32_t chx = (uint32_t)(((2 * (ks) + cb) ^ sw7) << 4);            \
            uint32_t b[16];                                                     \
            _Pragma("unroll")                                                   \
            for (int pp = 0; pp < 4; pp++)                                      \
                ldsm_x4(b + pp * 4, lmbase + (uint32_t)(pp * 4096) + chx);      \
            _Pragma("unroll")                                                   \
            for (int p = 0; p < 8; p++)                                         \
                mma16816(acc[p], fa0, fa1, fa2, fa3, b[p * 2], b[p * 2 + 1]);   \
            mma16816(zc, fa0, fa1, fa2, fa3, ONES, ONES);                       \
        } while (0)

    for (int lt = 0; lt < 16; lt++) {
        int s = lt & 1;
        __syncthreads();

        // issue next-tile B loads NOW; store after step 2
        uint4 v0, v1, v2, v3;
        bool refill = (lt < 15);
        if (refill) {
            const uint4* bs = bsrc_base + (lt + 1) * 16;
            v0 = bs[qb]; v1 = bs[qb + 1]; v2 = bs[qb + 2]; v3 = bs[qb + 3];
        }

        uint32_t lmbase = sb_base + (uint32_t)s * 16384u + (uint32_t)fo * 256u;
        int gbase = lt * 8;
        const int* gLt = gL + (gbase + 8) * 16;
        const int* gHt = gH + (gbase + 8) * 16;

        STEP(0); STEP(1); STEP(2);

        if (refill) {   // B deinterleave + store, ~350 cyc after the loads
            char* db = sBreg + (s ^ 1) * 16384 + (size_t)fB * 256;
            uint4 o0 = make_uint4(v0.x, v0.z, v1.x, v1.z);
            uint4 o1 = make_uint4(v0.y, v0.w, v1.y, v1.w);
            uint4 o2 = make_uint4(v2.x, v2.z, v3.x, v3.z);
            uint4 o3 = make_uint4(v2.y, v2.w, v3.y, v3.w);
            *(uint4*)(db + (((qb + 0) ^ (fB & 7)) << 4)) = o0;
            *(uint4*)(db + (((qb + 1) ^ (fB & 7)) << 4)) = o1;
            *(uint4*)(db + (((qb + 2) ^ (fB & 7)) << 4)) = o2;
            *(uint4*)(db + (((qb + 3) ^ (fB & 7)) << 4)) = o3;
        }

        STEP(3); STEP(4); STEP(5); STEP(6); STEP(7);
    }
    #undef STEP

    // epilogue: C frags -> g_part (stride 68, float2-aligned)
    size_t rbase = (size_t)bx * 128 + row0;
    #pragma unroll
    for (int p = 0; p < 8; p++) {
        float* o0 = g_part + rbase * 68 + p * 8 + l4 * 2;
        float* o1 = o0 + 8 * 68;
        *(float2*)o0 = make_float2(acc[p][0], acc[p][1]);
        *(float2*)o1 = make_float2(acc[p][2], acc[p][3]);
    }
    if (l4 == 0) {
        g_part[rbase * 68 + 64] = zc[0];
        g_part[(rbase + 8) * 68 + 64] = zc[2];
    }
}

// ---------------------------------------------------------------------------
// Kernel 3: combine 4 j-quarter partials, normalize, ELU.
// 16 rows per block; Z-sums computed ONCE per row into smem (kills the 64
// redundant scalar loads/row that latency-bound the old version); each
// thread then does 4 independent float4 loads (MLP 4).
// ---------------------------------------------------------------------------
__global__ __launch_bounds__(256) void combine_kernel(float* __restrict__ out) {
    __shared__ float zs[16];
    int t = threadIdx.x;
    int i0 = blockIdx.x * 16;                   // first node row of this block

    if (t < 16) {
        int i = i0 + t;
        int b0 = (i >> 7) * 4, r = i & 127;
        const float* pz = g_part + (size_t)(b0 * 128 + r) * 68 + 64;
        float z = 0.f;
        #pragma unroll
        for (int q = 0; q < 4; q++) z += pz[(size_t)q * 128 * 68];
        zs[t] = z;
    }
    __syncthreads();

    int lrow = t >> 4, fq = t & 15;
    int i = i0 + lrow;
    int b0 = (i >> 7) * 4, r = i & 127;
    const float* p = g_part + (size_t)(b0 * 128 + r) * 68 + fq * 4;
    float nx = 0.f, ny = 0.f, nz = 0.f, nw = 0.f;
    #pragma unroll
    for (int q = 0; q < 4; q++) {
        float4 v = *(const float4*)(p + (size_t)q * 128 * 68);
        nx += v.x; ny += v.y; nz += v.z; nw += v.w;
    }
    float z = zs[lrow];
    float4 o;
    o.x = nx / z; o.y = ny / z; o.z = nz / z; o.w = nw / z;
    o.x = (o.x > 0.f) ? o.x : expm1f(o.x);
    o.y = (o.y > 0.f) ? o.y : expm1f(o.y);
    o.z = (o.z > 0.f) ? o.z : expm1f(o.z);
    o.w = (o.w > 0.f) ? o.w : expm1f(o.w);
    *(float4*)(out + (size_t)i * F_OUTD + fq * 4) = o;
}

// ---------------------------------------------------------------------------
// Launch. Inputs: 0 h_nodes(8192x128 f32), 1 edge(8192 f32), 2 adj(8192^2 i32),
//                 3 weight(128x64 f32), 4 att(192 f32), 5 w_edge(64 f32)
// ---------------------------------------------------------------------------
extern "C" void kernel_launch(void* const* d_in, const int* in_sizes, int n_in,
                              void* d_out, int out_size) {
    const float* h      = (const float*)d_in[0];
    const float* edge   = (const float*)d_in[1];
    const int*   adj    = (const int*)d_in[2];
    const float* weight = (const float*)d_in[3];
    const float* att    = (const float*)d_in[4];
    const float* w_edge = (const float*)d_in[5];
    float* out = (float*)d_out;

    cudaFuncSetAttribute(attn_kernel,
                         cudaFuncAttributeMaxDynamicSharedMemorySize, 98304);

    prep_kernel<<<NN / 32, 256>>>(h, weight, edge, att, w_edge);
    attn_kernel<<<256, 256, 98304>>>(adj);
    combine_kernel<<<NN / 16, 256>>>(out);
}